// round 7
// baseline (speedup 1.0000x reference)
#include <cuda_runtime.h>
#include <cuda_bf16.h>

// NnHalfKA fused NNUE, round 5:
//   Kernel 1: W_comb[f] = bf16(W_ft[f] + W_fft[f % 768])  (rebuilt every launch)
//   Kernel 2: gather — 64 threads/CTA, 16B (uint4 = 8 bf16 cols) per thread,
//             smem-staged indices, 32-bit byte addressing, fp32 accum,
//             bias + clip + dot(W_out) + sigmoid fused.
//
// R4 gather was issue-bound (issue 47%, no pipe >40%): redundant uniform
// index LDGs + 64-bit address IMADs + 2x more load instrs than needed.

#define F_FULL   49152
#define F_VIRT   768
#define FT_DIM   512
#define GTHREADS 64
#define CHUNK    64

// 49152 * 512 bf16 = 50.3 MB static device scratch (allowed; no allocation).
__device__ __nv_bfloat16 g_wcomb[(size_t)F_FULL * FT_DIM];

__device__ __forceinline__ float clip01(float x) {
    return fminf(fmaxf(x, 0.0f), 1.0f);
}

// ---------------------------------------------------------------------------
// Kernel 1: build combined bf16 table. One thread per float4 (4 columns).
// ---------------------------------------------------------------------------
__global__ __launch_bounds__(256)
void build_comb_kernel(const float* __restrict__ W_ft,
                       const float* __restrict__ W_fft)
{
    const int idx = blockIdx.x * 256 + threadIdx.x;   // float4 index
    const int f   = idx >> 7;                         // 128 float4 per row
    const int c4  = idx & 127;

    const float4 a = __ldg((const float4*)W_ft + idx);
    const float4 b = __ldg((const float4*)W_fft + (f % F_VIRT) * 128 + c4);

    __nv_bfloat162 lo = __floats2bfloat162_rn(a.x + b.x, a.y + b.y);
    __nv_bfloat162 hi = __floats2bfloat162_rn(a.z + b.z, a.w + b.w);

    uint2 p;
    p.x = *reinterpret_cast<unsigned*>(&lo);
    p.y = *reinterpret_cast<unsigned*>(&hi);
    reinterpret_cast<uint2*>(g_wcomb)[idx] = p;
}

// ---------------------------------------------------------------------------
// Kernel 2: one CTA (64 threads) per batch row. Thread t owns 8 columns
// [8t, 8t+8) as one uint4 (16 bytes of bf16).
// ---------------------------------------------------------------------------
__device__ __forceinline__ void acc_uint4(const uint4& r, float v, float* acc) {
    const __nv_bfloat162* h = reinterpret_cast<const __nv_bfloat162*>(&r);
    #pragma unroll
    for (int q = 0; q < 4; ++q) {
        float2 f = __bfloat1622float2(h[q]);
        acc[2*q + 0] = fmaf(f.x, v, acc[2*q + 0]);
        acc[2*q + 1] = fmaf(f.y, v, acc[2*q + 1]);
    }
}

__global__ __launch_bounds__(GTHREADS)
void nnue_gather_kernel(const float* __restrict__ values,
                        const float* __restrict__ ft_b,
                        const float* __restrict__ fft_b,
                        const float* __restrict__ W_out,
                        const float* __restrict__ out_b,
                        const int*   __restrict__ batch_ids,
                        const int*   __restrict__ stm_feat,
                        const int*   __restrict__ nstm_feat,
                        float*       __restrict__ out,
                        int nnz)
{
    const int b = blockIdx.x;
    const int t = threadIdx.x;

    __shared__ int   s_range[2];
    __shared__ int   s_fs[CHUNK];
    __shared__ int   s_fn[CHUNK];
    __shared__ float s_v[CHUNK];
    __shared__ float s_red[GTHREADS / 32];

    // Segment bounds via binary search on sorted batch_ids (2 threads).
    if (t < 2) {
        int lo = 0, hi = nnz;
        while (lo < hi) {
            int m = (lo + hi) >> 1;
            bool go = (t == 0) ? (__ldg(batch_ids + m) < b)
                               : (__ldg(batch_ids + m) <= b);
            if (go) lo = m + 1; else hi = m;
        }
        s_range[t] = lo;
    }
    __syncthreads();
    const int start = s_range[0];
    const int end   = s_range[1];

    // Base pointer pre-offset by this thread's byte column (t*16).
    const char* __restrict__ wbase = reinterpret_cast<const char*>(g_wcomb) + (t << 4);

    float accs[8] = {0,0,0,0,0,0,0,0};
    float accn[8] = {0,0,0,0,0,0,0,0};

    for (int base = start; base < end; base += CHUNK) {
        const int n = min(CHUNK, end - base);
        // Cooperative index/value staging (one LDG per chunk element).
        if (t < n) {
            s_fs[t] = __ldg(stm_feat + base + t);
            s_fn[t] = __ldg(nstm_feat + base + t);
            s_v[t]  = __ldg(values + base + t);
        }
        __syncthreads();

        #pragma unroll 4
        for (int j = 0; j < n; ++j) {
            const unsigned ofs = (unsigned)s_fs[j] << 10;   // row * 1024 bytes
            const unsigned ofn = (unsigned)s_fn[j] << 10;
            const float    v   = s_v[j];

            const uint4 rs = __ldg(reinterpret_cast<const uint4*>(wbase + ofs));
            const uint4 rn = __ldg(reinterpret_cast<const uint4*>(wbase + ofn));

            acc_uint4(rs, v, accs);
            acc_uint4(rn, v, accn);
        }
        __syncthreads();
    }

    // Bias, clip, dot with W_out fragments (all fp32, exact).
    const int c = t * 8;
    float p = 0.f;
    #pragma unroll
    for (int q = 0; q < 8; ++q) {
        const float bias = __ldg(ft_b + c + q) + __ldg(fft_b + c + q);
        p = fmaf(clip01(accs[q] + bias), __ldg(W_out + c + q), p);
        p = fmaf(clip01(accn[q] + bias), __ldg(W_out + FT_DIM + c + q), p);
    }

    // Reduction across 64 threads (2 warps).
    #pragma unroll
    for (int off = 16; off > 0; off >>= 1)
        p += __shfl_down_sync(0xffffffffu, p, off);
    if ((t & 31) == 0) s_red[t >> 5] = p;
    __syncthreads();

    if (t == 0) {
        float tot = s_red[0] + s_red[1] + __ldg(out_b);
        out[b] = 1.0f / (1.0f + expf(-tot));
    }
}

extern "C" void kernel_launch(void* const* d_in, const int* in_sizes, int n_in,
                              void* d_out, int out_size) {
    const float* values    = (const float*)d_in[0];
    const float* W_ft      = (const float*)d_in[1];
    const float* ft_b      = (const float*)d_in[2];
    const float* W_fft     = (const float*)d_in[3];
    const float* fft_b     = (const float*)d_in[4];
    const float* W_out     = (const float*)d_in[5];
    const float* out_b     = (const float*)d_in[6];
    const int*   batch_ids = (const int*)d_in[7];
    const int*   stm_feat  = (const int*)d_in[8];
    const int*   nstm_feat = (const int*)d_in[9];
    float*       out       = (float*)d_out;

    const int nnz = in_sizes[0];
    const int B   = out_size;

    const int total_f4 = (F_FULL * FT_DIM) / 4;          // 6,291,456
    build_comb_kernel<<<total_f4 / 256, 256>>>(W_ft, W_fft);

    nnue_gather_kernel<<<B, GTHREADS>>>(values, ft_b, fft_b,
                                        W_out, out_b, batch_ids,
                                        stm_feat, nstm_feat, out, nnz);
}